// round 13
// baseline (speedup 1.0000x reference)
#include <cuda_runtime.h>
#include <math.h>

#define Hc 256
#define Wc 256
#define KY 32
#define NIMG 256

// ---------------- scratch ----------------
__device__ float2 g_T [NIMG * Hc * KY];        // A out [img][h][ky]
__device__ float2 g_XP[4 * NIMG * 64 * KY];    // B partials [hs][img][kx][ky]
__device__ float2 g_Y [NIMG * 2048];           // C out [img][p][mm][ky]
__device__ float2 g_T2[NIMG * Hc * KY];        // D out [img][h][ky]
// tables
__device__ float2 g_csA [128 * 32];            // [w][ky] cos,sin 2pi*ky*w/256
__device__ float2 g_E2  [128 * 32];            // [h'][mm] cos,sin 2pi*m*h'/128
__device__ float2 g_w256[128];                 // cos,sin 2pi*h/256
__device__ float2 g_cs2E[32 * 64];             // [ky][s] c*(cos,sin)(2pi*ky*(s+1)/256)

// ---------------- tables (fp64 exact) ----------------
__global__ void k_tables() {
    int idx = blockIdx.x * blockDim.x + threadIdx.x;
    const double TP = 6.283185307179586476925286766559;
    if (idx < 4096) {                          // csA
        int w = idx >> 5, ky = idx & 31;
        double a = TP * (double)((ky * w) & 255) / 256.0;
        g_csA[idx] = make_float2((float)cos(a), (float)sin(a));
        return;
    }
    idx -= 4096;
    if (idx < 4096) {                          // E2
        int hp = idx >> 5, mm = idx & 31;
        int m = (mm < 16) ? mm : mm + 96;
        double a = TP * (double)((m * hp) & 127) / 128.0;
        g_E2[idx] = make_float2((float)cos(a), (float)sin(a));
        return;
    }
    idx -= 4096;
    if (idx < 128) {                           // w256
        double a = TP * (double)idx / 256.0;
        g_w256[idx] = make_float2((float)cos(a), (float)sin(a));
        return;
    }
    idx -= 128;
    if (idx < 2048) {                          // cs2E
        int ky = idx >> 6, s = idx & 63;
        int tw = s + 1;
        double c = ((ky == 0) ? 1.0 : 2.0) / 65536.0;
        double a = TP * (double)((ky * tw) & 255) / 256.0;
        g_cs2E[idx] = make_float2((float)(c * cos(a)), (float)(c * sin(a)));
    }
}

// ------- stage A: doubly-folded W-DFT (u/v + ky-parity) --------------------
__global__ void __launch_bounds__(128) kA(const float* __restrict__ x) {
    __shared__ __align__(16) float sue[16 * 76];
    __shared__ __align__(16) float suo[16 * 76];
    __shared__ __align__(16) float sve[16 * 76];
    __shared__ __align__(16) float svo[16 * 76];
    __shared__ __align__(16) float2 scs[16 * 34];
    int img = blockIdx.y, hb = blockIdx.x;      // 64 h per block
    int t = threadIdx.x;
    int hg  = t & 15;                           // h_local = hg*4 + j
    int ky0 = (t >> 4) * 4;
    const float* xp = x + (size_t)img * 65536 + (size_t)hb * 64 * 256;

    float tr[4][4], ti[4][4];
#pragma unroll
    for (int j = 0; j < 4; j++)
#pragma unroll
        for (int q = 0; q < 4; q++) { tr[j][q] = 0.f; ti[j][q] = 0.f; }

    for (int wc = 0; wc < 4; wc++) {
#pragma unroll
        for (int r = 0; r < 8; r++) {
            int e = t + r * 128;
            int wl = e & 15, hh = e >> 4;
            int w = wc * 16 + wl + 1;           // 1..64
            float a1 = xp[hh * 256 + w];
            float b1 = xp[hh * 256 + 256 - w];
            float a2 = xp[hh * 256 + 128 - w];
            float b2 = xp[hh * 256 + 128 + w];
            float u1 = a1 + b1, v1 = a1 - b1;
            float u2 = a2 + b2, v2 = a2 - b2;
            float ue = u1 + u2, uo = u1 - u2;
            float ve = v1 - v2, vo = v1 + v2;
            if (w == 64) { ue = 0.f; uo = 0.f; ve = 0.f; vo = 0.f; }
            sue[wl * 76 + hh] = ue;
            suo[wl * 76 + hh] = uo;
            sve[wl * 76 + hh] = ve;
            svo[wl * 76 + hh] = vo;
        }
#pragma unroll
        for (int r = 0; r < 4; r++) {
            int e = t + r * 128;
            int ky = e & 31, wl = e >> 5;
            scs[wl * 34 + ky] = g_csA[(wc * 16 + wl + 1) * 32 + ky];
        }
        __syncthreads();
#pragma unroll 8
        for (int wl = 0; wl < 16; wl++) {
            float4 ue = *(const float4*)&sue[wl * 76 + hg * 4];
            float4 uo = *(const float4*)&suo[wl * 76 + hg * 4];
            float4 ve = *(const float4*)&sve[wl * 76 + hg * 4];
            float4 vo = *(const float4*)&svo[wl * 76 + hg * 4];
            float uev[4] = {ue.x, ue.y, ue.z, ue.w};
            float uov[4] = {uo.x, uo.y, uo.z, uo.w};
            float vev[4] = {ve.x, ve.y, ve.z, ve.w};
            float vov[4] = {vo.x, vo.y, vo.z, vo.w};
            float4 c01 = *(const float4*)&scs[wl * 34 + ky0];
            float4 c23 = *(const float4*)&scs[wl * 34 + ky0 + 2];
            float cc[4] = {c01.x, c01.z, c23.x, c23.z};
            float ss[4] = {c01.y, c01.w, c23.y, c23.w};
#pragma unroll
            for (int j = 0; j < 4; j++) {
                tr[j][0] += uev[j] * cc[0];  ti[j][0] -= vev[j] * ss[0];
                tr[j][1] += uov[j] * cc[1];  ti[j][1] -= vov[j] * ss[1];
                tr[j][2] += uev[j] * cc[2];  ti[j][2] -= vev[j] * ss[2];
                tr[j][3] += uov[j] * cc[3];  ti[j][3] -= vov[j] * ss[3];
            }
        }
        __syncthreads();
    }
    // specials: w = 0, 64, 128
#pragma unroll
    for (int j = 0; j < 4; j++) {
        int hh = hg * 4 + j;
        float x0   = xp[hh * 256];
        float x64  = xp[hh * 256 + 64];
        float x128 = xp[hh * 256 + 128];
        float x192 = xp[hh * 256 + 192];
        float u64v = x64 + x192, v64v = x64 - x192;
        tr[j][0] += x0 + u64v + x128;
        tr[j][1] += x0 - x128;
        tr[j][2] += x0 - u64v + x128;
        tr[j][3] += x0 - x128;
        ti[j][1] -= v64v;
        ti[j][3] += v64v;
    }
#pragma unroll
    for (int j = 0; j < 4; j++) {
        int h = hb * 64 + hg * 4 + j;
        size_t base = ((size_t)img * Hc + h) * KY + ky0;
        *(float4*)&g_T[base]     = make_float4(tr[j][0], ti[j][0], tr[j][1], ti[j][1]);
        *(float4*)&g_T[base + 2] = make_float4(tr[j][2], ti[j][2], tr[j][3], ti[j][3]);
    }
}

// ------- stage B: radix-2 H-DFT. Block = 32 h' chunk; outputs kx=2mm,2mm+1 --
__global__ void __launch_bounds__(128) kB() {
    __shared__ __align__(16) float2 Ut[32 * 34];
    __shared__ __align__(16) float2 Vt[32 * 34];
    __shared__ float2 Et[32 * 34];
    int img = blockIdx.y, hs = blockIdx.x;
    int h0 = hs * 32;
    int t = threadIdx.x;
    int ky0 = (t & 7) * 4;
    int mm0 = (t >> 3) * 2;

    float er[2][2][4], ei[2][2][4];   // [parity][m][ky]
#pragma unroll
    for (int p = 0; p < 2; p++)
#pragma unroll
        for (int m = 0; m < 2; m++)
#pragma unroll
            for (int q = 0; q < 4; q++) { er[p][m][q] = 0.f; ei[p][m][q] = 0.f; }

#pragma unroll
    for (int r = 0; r < 8; r++) {
        int e = t + r * 128; int hh = e >> 5, kk = e & 31;
        size_t ia = ((size_t)img * Hc + h0 + hh) * KY + kk;
        size_t ib = ((size_t)img * Hc + h0 + hh + 128) * KY + kk;
        float2 a = g_T[ia];
        float2 b = g_T[ib];
        Ut[hh * 34 + kk] = make_float2(a.x + b.x, a.y + b.y);
        float dx = a.x - b.x, dy = a.y - b.y;
        float2 w = g_w256[h0 + hh];   // e^{-i th}: (c,-s)
        Vt[hh * 34 + kk] = make_float2(dx * w.x + dy * w.y, dy * w.x - dx * w.y);
        Et[hh * 34 + kk] = g_E2[(h0 + hh) * 32 + kk];
    }
    __syncthreads();
#pragma unroll 4
    for (int hh = 0; hh < 32; hh++) {
        float4 u01 = *(const float4*)&Ut[hh * 34 + ky0];
        float4 u23 = *(const float4*)&Ut[hh * 34 + ky0 + 2];
        float4 v01 = *(const float4*)&Vt[hh * 34 + ky0];
        float4 v23 = *(const float4*)&Vt[hh * 34 + ky0 + 2];
        float ur[4] = {u01.x, u01.z, u23.x, u23.z};
        float ui[4] = {u01.y, u01.w, u23.y, u23.w};
        float vr[4] = {v01.x, v01.z, v23.x, v23.z};
        float vi[4] = {v01.y, v01.w, v23.y, v23.w};
#pragma unroll
        for (int m = 0; m < 2; m++) {
            float2 e = Et[hh * 34 + mm0 + m];
#pragma unroll
            for (int q = 0; q < 4; q++) {
                er[0][m][q] += e.x * ur[q] + e.y * ui[q];
                ei[0][m][q] += e.x * ui[q] - e.y * ur[q];
                er[1][m][q] += e.x * vr[q] + e.y * vi[q];
                ei[1][m][q] += e.x * vi[q] - e.y * vr[q];
            }
        }
    }
#pragma unroll
    for (int m = 0; m < 2; m++)
#pragma unroll
        for (int p = 0; p < 2; p++) {
            int kx = 2 * (mm0 + m) + p;
            size_t base = (size_t)hs * 524288 + (size_t)img * 2048 + kx * 32 + ky0;
            *(float4*)&g_XP[base] =
                make_float4(er[p][m][0], ei[p][m][0], er[p][m][1], ei[p][m][1]);
            *(float4*)&g_XP[base + 2] =
                make_float4(er[p][m][2], ei[p][m][2], er[p][m][3], ei[p][m][3]);
        }
}

// ------- stage C: fused weight load (float4 rows) + partial-sum + mix ------
__global__ void __launch_bounds__(256) kC(const float* __restrict__ w1r,
                                          const float* __restrict__ w1i,
                                          const float* __restrict__ w2r,
                                          const float* __restrict__ w2i) {
    __shared__ float2 Ws[4 * 1028];                 // [kkl][io], stride 1028
    __shared__ __align__(16) float2 Xs[256 * 4];    // [img][kkl]
    int kk0 = blockIdx.x * 4;
    int t = threadIdx.x;
    // weights: one aligned float4 per io row covers all 4 kkl columns
    int z = kk0 >> 10, c = kk0 & 1023;
    const float* wr = z ? w2r : w1r;
    const float* wi = z ? w2i : w1i;
#pragma unroll
    for (int r = 0; r < 4; r++) {
        int io = t + r * 256;
        float4 fr = *(const float4*)&wr[(size_t)io * 1024 + c];
        float4 fi = *(const float4*)&wi[(size_t)io * 1024 + c];
        Ws[0 * 1028 + io] = make_float2(fr.x, fi.x);
        Ws[1 * 1028 + io] = make_float2(fr.y, fi.y);
        Ws[2 * 1028 + io] = make_float2(fr.z, fi.z);
        Ws[3 * 1028 + io] = make_float2(fr.w, fi.w);
    }
    // partial sum: lanes 0-3 cover the 4 kk -> full 32B sectors
#pragma unroll
    for (int r = 0; r < 4; r++) {
        int e = t + r * 256;
        int img = e >> 2, kkl = e & 3;
        size_t base = (size_t)img * 2048 + kk0 + kkl;
        float2 s = g_XP[base];
#pragma unroll
        for (int p = 1; p < 4; p++) {
            float2 v = g_XP[(size_t)p * 524288 + base];
            s.x += v.x; s.y += v.y;
        }
        Xs[e] = s;
    }
    __syncthreads();
    int b = t >> 5, o = t & 31;
    float yr[4], yi[4];
#pragma unroll
    for (int k = 0; k < 4; k++) { yr[k] = 0.f; yi[k] = 0.f; }
#pragma unroll
    for (int i = 0; i < 32; i++) {
        float4 xA = *(const float4*)&Xs[(b * 32 + i) * 4];
        float4 xB = *(const float4*)&Xs[(b * 32 + i) * 4 + 2];
        float xvr[4] = {xA.x, xA.z, xB.x, xB.z};
        float xvi[4] = {xA.y, xA.w, xB.y, xB.w};
#pragma unroll
        for (int k = 0; k < 4; k++) {
            float2 wv = Ws[k * 1028 + i * 32 + o];
            yr[k] += xvr[k] * wv.x - xvi[k] * wv.y;
            yi[k] += xvr[k] * wv.y + xvi[k] * wv.x;
        }
    }
    int p = (kk0 >> 5) & 1, mm = kk0 >> 6, ky = kk0 & 31;
    size_t obase = (size_t)t * 2048 + p * 1024 + mm * 32 + ky;
#pragma unroll
    for (int k = 0; k < 4; k++)
        g_Y[obase + k] = make_float2(yr[k], yi[k]);
}

// ------- stage D: radix-2 inverse H-DFT. Block = 32 h' -> 64 output rows ---
__global__ void __launch_bounds__(128) kD() {
    __shared__ __align__(16) float2 Ye[32 * 34];
    __shared__ __align__(16) float2 Yo[32 * 34];
    __shared__ float2 Eh[32 * 34];
    int img = blockIdx.y, hs = blockIdx.x;
    int h0 = hs * 32;
    int t = threadIdx.x;
    int ky0 = (t & 7) * 4;
    int hl  = (t >> 3) * 2;

#pragma unroll
    for (int r = 0; r < 8; r++) {
        int e = t + r * 128; int a = e >> 5, b = e & 31;
        Ye[a * 34 + b] = g_Y[(size_t)img * 2048 + a * 32 + b];
        Yo[a * 34 + b] = g_Y[(size_t)img * 2048 + 1024 + a * 32 + b];
        Eh[a * 34 + b] = g_E2[(h0 + a) * 32 + b];
    }
    __syncthreads();

    float aer[2][4], aei[2][4], aor[2][4], aoi[2][4];
#pragma unroll
    for (int j = 0; j < 2; j++)
#pragma unroll
        for (int q = 0; q < 4; q++) { aer[j][q]=0.f; aei[j][q]=0.f; aor[j][q]=0.f; aoi[j][q]=0.f; }

#pragma unroll 4
    for (int mm = 0; mm < 32; mm++) {
        float4 e01 = *(const float4*)&Ye[mm * 34 + ky0];
        float4 e23 = *(const float4*)&Ye[mm * 34 + ky0 + 2];
        float4 o01 = *(const float4*)&Yo[mm * 34 + ky0];
        float4 o23 = *(const float4*)&Yo[mm * 34 + ky0 + 2];
        float yer[4] = {e01.x, e01.z, e23.x, e23.z};
        float yei[4] = {e01.y, e01.w, e23.y, e23.w};
        float yor[4] = {o01.x, o01.z, o23.x, o23.z};
        float yoi[4] = {o01.y, o01.w, o23.y, o23.w};
#pragma unroll
        for (int j = 0; j < 2; j++) {
            float2 e = Eh[(hl + j) * 34 + mm];
#pragma unroll
            for (int q = 0; q < 4; q++) {
                aer[j][q] += e.x * yer[q] - e.y * yei[q];
                aei[j][q] += e.x * yei[q] + e.y * yer[q];
                aor[j][q] += e.x * yor[q] - e.y * yoi[q];
                aoi[j][q] += e.x * yoi[q] + e.y * yor[q];
            }
        }
    }
#pragma unroll
    for (int j = 0; j < 2; j++) {
        int hp = h0 + hl + j;
        float2 w = g_w256[hp];
        float pr[4], pi[4], mr[4], mi[4];
#pragma unroll
        for (int q = 0; q < 4; q++) {
            float sr = aor[j][q] * w.x - aoi[j][q] * w.y;
            float si = aoi[j][q] * w.x + aor[j][q] * w.y;
            pr[q] = aer[j][q] + sr; pi[q] = aei[j][q] + si;
            mr[q] = aer[j][q] - sr; mi[q] = aei[j][q] - si;
        }
        size_t b1 = ((size_t)img * Hc + hp) * KY + ky0;
        size_t b2 = ((size_t)img * Hc + hp + 128) * KY + ky0;
        *(float4*)&g_T2[b1]     = make_float4(pr[0], pi[0], pr[1], pi[1]);
        *(float4*)&g_T2[b1 + 2] = make_float4(pr[2], pi[2], pr[3], pi[3]);
        *(float4*)&g_T2[b2]     = make_float4(mr[0], mi[0], mr[1], mi[1]);
        *(float4*)&g_T2[b2 + 2] = make_float4(mr[2], mi[2], mr[3], mi[3]);
    }
}

// ------- stage E: ky-parity-folded inverse W-DFT + w0/w128 columns ---------
__global__ void __launch_bounds__(256) kE(const float* __restrict__ bias,
                                          float* __restrict__ out) {
    __shared__ __align__(16) float2 T2s[32 * 66];   // [ky][h]
    __shared__ __align__(16) float2 csE[32 * 34];   // [ky][s_local]
    int img = blockIdx.z;
    int hb  = blockIdx.y;            // 0..3 (64 h)
    int wb  = blockIdx.x;            // 0..1 (32 s)
    int t = threadIdx.x;
    int sl = t & 15;                 // s = sl and sl+16
    int hq = (t >> 4) * 4;           // 4 h per thread

#pragma unroll
    for (int r = 0; r < 8; r++) {
        int e = t + r * 256; int ky = e & 31, h = e >> 5;
        T2s[ky * 66 + h] = g_T2[((size_t)img * Hc + hb * 64 + h) * KY + ky];
    }
#pragma unroll
    for (int r = 0; r < 4; r++) {
        int e = t + r * 256; int ky = e >> 5, s = e & 31;
        csE[ky * 34 + s] = g_cs2E[ky * 64 + wb * 32 + s];
    }
    __syncthreads();

    float Pe[4][2], Po[4][2], Qe[4][2], Qo[4][2];
#pragma unroll
    for (int j = 0; j < 4; j++)
#pragma unroll
        for (int q = 0; q < 2; q++) { Pe[j][q]=0.f; Po[j][q]=0.f; Qe[j][q]=0.f; Qo[j][q]=0.f; }

#pragma unroll
    for (int ky = 0; ky < 32; ky++) {
        float4 t01 = *(const float4*)&T2s[ky * 66 + hq];
        float4 t23 = *(const float4*)&T2s[ky * 66 + hq + 2];
        float trv[4] = {t01.x, t01.z, t23.x, t23.z};
        float tiv[4] = {t01.y, t01.w, t23.y, t23.w};
        float2 ca = csE[ky * 34 + sl];
        float2 cb = csE[ky * 34 + sl + 16];
        float cc[2] = {ca.x, cb.x};
        float ss[2] = {ca.y, cb.y};
        if ((ky & 1) == 0) {
#pragma unroll
            for (int j = 0; j < 4; j++)
#pragma unroll
                for (int q = 0; q < 2; q++) {
                    Pe[j][q] += cc[q] * trv[j];
                    Qe[j][q] += ss[q] * tiv[j];
                }
        } else {
#pragma unroll
            for (int j = 0; j < 4; j++)
#pragma unroll
                for (int q = 0; q < 2; q++) {
                    Po[j][q] += cc[q] * trv[j];
                    Qo[j][q] += ss[q] * tiv[j];
                }
        }
    }

    float bv = bias[img & 31];
#pragma unroll
    for (int j = 0; j < 4; j++) {
        size_t row = ((size_t)img * Hc + hb * 64 + hq + j) * Wc;
#pragma unroll
        for (int q = 0; q < 2; q++) {
            int tw = wb * 32 + sl + 16 * q + 1;    // half-warp writes 16 consecutive w
            float Pp = Pe[j][q] + Po[j][q], Pm = Pe[j][q] - Po[j][q];
            float Qp = Qe[j][q] + Qo[j][q], Qm = Qe[j][q] - Qo[j][q];
            out[row + tw]        = Pp - Qp + bv;
            out[row + 256 - tw]  = Pp + Qp + bv;
            out[row + 128 - tw]  = Pm + Qm + bv;
            out[row + 128 + tw]  = Pm - Qm + bv;
        }
    }

    // merged former kE0: w = 0 and w = 128 columns (lanes sl<2 of wb==0)
    if (wb == 0 && sl < 2) {
        float acc[4] = {0.f, 0.f, 0.f, 0.f};
#pragma unroll 8
        for (int ky = 0; ky < 32; ky++) {
            float coef = ((ky == 0) ? 1.f : 2.f) * (1.f / 65536.f);
            float f = (sl == 1 && (ky & 1)) ? -coef : coef;
#pragma unroll
            for (int j = 0; j < 4; j++)
                acc[j] += f * T2s[ky * 66 + hq + j].x;
        }
        int wcol = (sl == 0) ? 0 : 128;
#pragma unroll
        for (int j = 0; j < 4; j++) {
            size_t row = ((size_t)img * Hc + hb * 64 + hq + j) * Wc;
            out[row + wcol] = acc[j] + bv;
        }
    }
}

// ---------------- launch ----------------
extern "C" void kernel_launch(void* const* d_in, const int* in_sizes, int n_in,
                              void* d_out, int out_size) {
    const float* x    = (const float*)d_in[0];
    const float* w1r  = (const float*)d_in[1];
    const float* w1i  = (const float*)d_in[2];
    const float* w2r  = (const float*)d_in[3];
    const float* w2i  = (const float*)d_in[4];
    const float* bias = (const float*)d_in[5];
    float* out = (float*)d_out;

    k_tables<<<48, 256>>>();
    kA<<<dim3(4, 256), 128>>>(x);
    kB<<<dim3(4, 256), 128>>>();
    kC<<<512, 256>>>(w1r, w1i, w2r, w2i);
    kD<<<dim3(4, 256), 128>>>();
    kE<<<dim3(2, 4, 256), 256>>>(bias, out);
}

// round 16
// speedup vs baseline: 1.0221x; 1.0221x over previous
#include <cuda_runtime.h>
#include <math.h>

#define Hc 256
#define Wc 256
#define KY 32
#define NIMG 256

// ---------------- scratch ----------------
__device__ float2 g_T [NIMG * Hc * KY];        // A out [img][h][ky]
__device__ float2 g_XP[4 * NIMG * 64 * KY];    // B partials [hs][img][kx][ky]
__device__ float2 g_Y [NIMG * 2048];           // C out [img][p][mm][ky]
__device__ float2 g_T2[NIMG * Hc * KY];        // D out [img][h][ky]
__device__ float2 g_Wt[2048 * 1024];           // [kx*32+ky][i*32+o]
// tables
__device__ float2 g_csA [128 * 32];            // [w][ky] cos,sin 2pi*ky*w/256
__device__ float2 g_E2  [128 * 32];            // [h'][mm] cos,sin 2pi*m*h'/128
__device__ float2 g_w256[128];                 // cos,sin 2pi*h/256
__device__ float2 g_cs2E[32 * 64];             // [ky][s] c*(cos,sin)(2pi*ky*(s+1)/256)

// ---------------- tables (fp64 exact) ----------------
__global__ void k_tables() {
    int idx = blockIdx.x * blockDim.x + threadIdx.x;
    const double TP = 6.283185307179586476925286766559;
    if (idx < 4096) {                          // csA
        int w = idx >> 5, ky = idx & 31;
        double a = TP * (double)((ky * w) & 255) / 256.0;
        g_csA[idx] = make_float2((float)cos(a), (float)sin(a));
        return;
    }
    idx -= 4096;
    if (idx < 4096) {                          // E2
        int hp = idx >> 5, mm = idx & 31;
        int m = (mm < 16) ? mm : mm + 96;
        double a = TP * (double)((m * hp) & 127) / 128.0;
        g_E2[idx] = make_float2((float)cos(a), (float)sin(a));
        return;
    }
    idx -= 4096;
    if (idx < 128) {                           // w256
        double a = TP * (double)idx / 256.0;
        g_w256[idx] = make_float2((float)cos(a), (float)sin(a));
        return;
    }
    idx -= 128;
    if (idx < 2048) {                          // cs2E
        int ky = idx >> 6, s = idx & 63;
        int tw = s + 1;
        double c = ((ky == 0) ? 1.0 : 2.0) / 65536.0;
        double a = TP * (double)((ky * tw) & 255) / 256.0;
        g_cs2E[idx] = make_float2((float)(c * cos(a)), (float)(c * sin(a)));
    }
}

// ---------------- weight transpose: [io][kxky] -> [kxky][io] ---------------
__global__ void k_wtrans(const float* __restrict__ w1r, const float* __restrict__ w1i,
                         const float* __restrict__ w2r, const float* __restrict__ w2i) {
    __shared__ float2 tile[32][33];
    int z = blockIdx.z;
    const float* wr = z ? w2r : w1r;
    const float* wi = z ? w2i : w1i;
    int col = blockIdx.x * 32 + threadIdx.x;
#pragma unroll
    for (int j = 0; j < 4; j++) {
        int row = blockIdx.y * 32 + threadIdx.y + j * 8;
        tile[threadIdx.y + j * 8][threadIdx.x] =
            make_float2(wr[row * 1024 + col], wi[row * 1024 + col]);
    }
    __syncthreads();
    int ocol = blockIdx.y * 32 + threadIdx.x;
#pragma unroll
    for (int j = 0; j < 4; j++) {
        int orow = z * 1024 + blockIdx.x * 32 + threadIdx.y + j * 8;
        g_Wt[(size_t)orow * 1024 + ocol] = tile[threadIdx.x][threadIdx.y + j * 8];
    }
}

// ------- stage A: doubly-folded W-DFT (u/v + ky-parity) --------------------
__global__ void __launch_bounds__(128) kA(const float* __restrict__ x) {
    __shared__ __align__(16) float sue[16 * 76];
    __shared__ __align__(16) float suo[16 * 76];
    __shared__ __align__(16) float sve[16 * 76];
    __shared__ __align__(16) float svo[16 * 76];
    __shared__ __align__(16) float2 scs[16 * 34];
    int img = blockIdx.y, hb = blockIdx.x;      // 64 h per block
    int t = threadIdx.x;
    int hg  = t & 15;                           // h_local = hg*4 + j
    int ky0 = (t >> 4) * 4;
    const float* xp = x + (size_t)img * 65536 + (size_t)hb * 64 * 256;

    float tr[4][4], ti[4][4];
#pragma unroll
    for (int j = 0; j < 4; j++)
#pragma unroll
        for (int q = 0; q < 4; q++) { tr[j][q] = 0.f; ti[j][q] = 0.f; }

    for (int wc = 0; wc < 4; wc++) {
#pragma unroll
        for (int r = 0; r < 8; r++) {
            int e = t + r * 128;
            int wl = e & 15, hh = e >> 4;
            int w = wc * 16 + wl + 1;           // 1..64
            float a1 = xp[hh * 256 + w];
            float b1 = xp[hh * 256 + 256 - w];
            float a2 = xp[hh * 256 + 128 - w];
            float b2 = xp[hh * 256 + 128 + w];
            float u1 = a1 + b1, v1 = a1 - b1;
            float u2 = a2 + b2, v2 = a2 - b2;
            float ue = u1 + u2, uo = u1 - u2;
            float ve = v1 - v2, vo = v1 + v2;
            if (w == 64) { ue = 0.f; uo = 0.f; ve = 0.f; vo = 0.f; }
            sue[wl * 76 + hh] = ue;
            suo[wl * 76 + hh] = uo;
            sve[wl * 76 + hh] = ve;
            svo[wl * 76 + hh] = vo;
        }
#pragma unroll
        for (int r = 0; r < 4; r++) {
            int e = t + r * 128;
            int ky = e & 31, wl = e >> 5;
            scs[wl * 34 + ky] = g_csA[(wc * 16 + wl + 1) * 32 + ky];
        }
        __syncthreads();
#pragma unroll 8
        for (int wl = 0; wl < 16; wl++) {
            float4 ue = *(const float4*)&sue[wl * 76 + hg * 4];
            float4 uo = *(const float4*)&suo[wl * 76 + hg * 4];
            float4 ve = *(const float4*)&sve[wl * 76 + hg * 4];
            float4 vo = *(const float4*)&svo[wl * 76 + hg * 4];
            float uev[4] = {ue.x, ue.y, ue.z, ue.w};
            float uov[4] = {uo.x, uo.y, uo.z, uo.w};
            float vev[4] = {ve.x, ve.y, ve.z, ve.w};
            float vov[4] = {vo.x, vo.y, vo.z, vo.w};
            float4 c01 = *(const float4*)&scs[wl * 34 + ky0];
            float4 c23 = *(const float4*)&scs[wl * 34 + ky0 + 2];
            float cc[4] = {c01.x, c01.z, c23.x, c23.z};
            float ss[4] = {c01.y, c01.w, c23.y, c23.w};
#pragma unroll
            for (int j = 0; j < 4; j++) {
                tr[j][0] += uev[j] * cc[0];  ti[j][0] -= vev[j] * ss[0];
                tr[j][1] += uov[j] * cc[1];  ti[j][1] -= vov[j] * ss[1];
                tr[j][2] += uev[j] * cc[2];  ti[j][2] -= vev[j] * ss[2];
                tr[j][3] += uov[j] * cc[3];  ti[j][3] -= vov[j] * ss[3];
            }
        }
        __syncthreads();
    }
    // specials: w = 0, 64, 128
#pragma unroll
    for (int j = 0; j < 4; j++) {
        int hh = hg * 4 + j;
        float x0   = xp[hh * 256];
        float x64  = xp[hh * 256 + 64];
        float x128 = xp[hh * 256 + 128];
        float x192 = xp[hh * 256 + 192];
        float u64v = x64 + x192, v64v = x64 - x192;
        tr[j][0] += x0 + u64v + x128;
        tr[j][1] += x0 - x128;
        tr[j][2] += x0 - u64v + x128;
        tr[j][3] += x0 - x128;
        ti[j][1] -= v64v;
        ti[j][3] += v64v;
    }
#pragma unroll
    for (int j = 0; j < 4; j++) {
        int h = hb * 64 + hg * 4 + j;
        size_t base = ((size_t)img * Hc + h) * KY + ky0;
        *(float4*)&g_T[base]     = make_float4(tr[j][0], ti[j][0], tr[j][1], ti[j][1]);
        *(float4*)&g_T[base + 2] = make_float4(tr[j][2], ti[j][2], tr[j][3], ti[j][3]);
    }
}

// ------- stage B: radix-2 H-DFT. Block = 32 h' chunk; outputs kx=2mm,2mm+1 --
__global__ void __launch_bounds__(128) kB() {
    __shared__ __align__(16) float2 Ut[32 * 34];
    __shared__ __align__(16) float2 Vt[32 * 34];
    __shared__ float2 Et[32 * 34];
    int img = blockIdx.y, hs = blockIdx.x;
    int h0 = hs * 32;
    int t = threadIdx.x;
    int ky0 = (t & 7) * 4;
    int mm0 = (t >> 3) * 2;

    float er[2][2][4], ei[2][2][4];   // [parity][m][ky]
#pragma unroll
    for (int p = 0; p < 2; p++)
#pragma unroll
        for (int m = 0; m < 2; m++)
#pragma unroll
            for (int q = 0; q < 4; q++) { er[p][m][q] = 0.f; ei[p][m][q] = 0.f; }

#pragma unroll
    for (int r = 0; r < 8; r++) {
        int e = t + r * 128; int hh = e >> 5, kk = e & 31;
        size_t ia = ((size_t)img * Hc + h0 + hh) * KY + kk;
        size_t ib = ((size_t)img * Hc + h0 + hh + 128) * KY + kk;
        float2 a = g_T[ia];
        float2 b = g_T[ib];
        Ut[hh * 34 + kk] = make_float2(a.x + b.x, a.y + b.y);
        float dx = a.x - b.x, dy = a.y - b.y;
        float2 w = g_w256[h0 + hh];   // e^{-i th}: (c,-s)
        Vt[hh * 34 + kk] = make_float2(dx * w.x + dy * w.y, dy * w.x - dx * w.y);
        Et[hh * 34 + kk] = g_E2[(h0 + hh) * 32 + kk];
    }
    __syncthreads();
#pragma unroll 4
    for (int hh = 0; hh < 32; hh++) {
        float4 u01 = *(const float4*)&Ut[hh * 34 + ky0];
        float4 u23 = *(const float4*)&Ut[hh * 34 + ky0 + 2];
        float4 v01 = *(const float4*)&Vt[hh * 34 + ky0];
        float4 v23 = *(const float4*)&Vt[hh * 34 + ky0 + 2];
        float ur[4] = {u01.x, u01.z, u23.x, u23.z};
        float ui[4] = {u01.y, u01.w, u23.y, u23.w};
        float vr[4] = {v01.x, v01.z, v23.x, v23.z};
        float vi[4] = {v01.y, v01.w, v23.y, v23.w};
#pragma unroll
        for (int m = 0; m < 2; m++) {
            float2 e = Et[hh * 34 + mm0 + m];
#pragma unroll
            for (int q = 0; q < 4; q++) {
                er[0][m][q] += e.x * ur[q] + e.y * ui[q];
                ei[0][m][q] += e.x * ui[q] - e.y * ur[q];
                er[1][m][q] += e.x * vr[q] + e.y * vi[q];
                ei[1][m][q] += e.x * vi[q] - e.y * vr[q];
            }
        }
    }
#pragma unroll
    for (int m = 0; m < 2; m++)
#pragma unroll
        for (int p = 0; p < 2; p++) {
            int kx = 2 * (mm0 + m) + p;
            size_t base = (size_t)hs * 524288 + (size_t)img * 2048 + kx * 32 + ky0;
            *(float4*)&g_XP[base] =
                make_float4(er[p][m][0], ei[p][m][0], er[p][m][1], ei[p][m][1]);
            *(float4*)&g_XP[base + 2] =
                make_float4(er[p][m][2], ei[p][m][2], er[p][m][3], ei[p][m][3]);
        }
}

// ------- stage C: coalesced partial-sum + channel mix (g_Wt reads) ---------
__global__ void __launch_bounds__(256) kC() {
    __shared__ float2 Ws[4 * 1024];                 // [kkl][io]
    __shared__ __align__(16) float2 Xs[256 * 4];    // [img][kkl]
    int kk0 = blockIdx.x * 4;
    int t = threadIdx.x;
    // weights: fully coalesced rows of g_Wt
#pragma unroll
    for (int r = 0; r < 16; r++) {
        int e = t + r * 256;
        Ws[e] = g_Wt[(size_t)kk0 * 1024 + e];
    }
    // partial sum: lanes 0-3 cover the 4 kk -> full 32B sectors
#pragma unroll
    for (int r = 0; r < 4; r++) {
        int e = t + r * 256;
        int img = e >> 2, kkl = e & 3;
        size_t base = (size_t)img * 2048 + kk0 + kkl;
        float2 s = g_XP[base];
#pragma unroll
        for (int p = 1; p < 4; p++) {
            float2 v = g_XP[(size_t)p * 524288 + base];
            s.x += v.x; s.y += v.y;
        }
        Xs[e] = s;
    }
    __syncthreads();
    int b = t >> 5, o = t & 31;
    float yr[4], yi[4];
#pragma unroll
    for (int k = 0; k < 4; k++) { yr[k] = 0.f; yi[k] = 0.f; }
#pragma unroll
    for (int i = 0; i < 32; i++) {
        float4 xA = *(const float4*)&Xs[(b * 32 + i) * 4];
        float4 xB = *(const float4*)&Xs[(b * 32 + i) * 4 + 2];
        float xvr[4] = {xA.x, xA.z, xB.x, xB.z};
        float xvi[4] = {xA.y, xA.w, xB.y, xB.w};
#pragma unroll
        for (int k = 0; k < 4; k++) {
            float2 wv = Ws[k * 1024 + i * 32 + o];
            yr[k] += xvr[k] * wv.x - xvi[k] * wv.y;
            yi[k] += xvr[k] * wv.y + xvi[k] * wv.x;
        }
    }
    int p = (kk0 >> 5) & 1, mm = kk0 >> 6, ky = kk0 & 31;
    size_t obase = (size_t)t * 2048 + p * 1024 + mm * 32 + ky;
#pragma unroll
    for (int k = 0; k < 4; k++)
        g_Y[obase + k] = make_float2(yr[k], yi[k]);
}

// ------- stage D: radix-2 inverse H-DFT. Block = 32 h' -> 64 output rows ---
__global__ void __launch_bounds__(128) kD() {
    __shared__ __align__(16) float2 Ye[32 * 34];
    __shared__ __align__(16) float2 Yo[32 * 34];
    __shared__ float2 Eh[32 * 34];
    int img = blockIdx.y, hs = blockIdx.x;
    int h0 = hs * 32;
    int t = threadIdx.x;
    int ky0 = (t & 7) * 4;
    int hl  = (t >> 3) * 2;

#pragma unroll
    for (int r = 0; r < 8; r++) {
        int e = t + r * 128; int a = e >> 5, b = e & 31;
        Ye[a * 34 + b] = g_Y[(size_t)img * 2048 + a * 32 + b];
        Yo[a * 34 + b] = g_Y[(size_t)img * 2048 + 1024 + a * 32 + b];
        Eh[a * 34 + b] = g_E2[(h0 + a) * 32 + b];
    }
    __syncthreads();

    float aer[2][4], aei[2][4], aor[2][4], aoi[2][4];
#pragma unroll
    for (int j = 0; j < 2; j++)
#pragma unroll
        for (int q = 0; q < 4; q++) { aer[j][q]=0.f; aei[j][q]=0.f; aor[j][q]=0.f; aoi[j][q]=0.f; }

#pragma unroll 4
    for (int mm = 0; mm < 32; mm++) {
        float4 e01 = *(const float4*)&Ye[mm * 34 + ky0];
        float4 e23 = *(const float4*)&Ye[mm * 34 + ky0 + 2];
        float4 o01 = *(const float4*)&Yo[mm * 34 + ky0];
        float4 o23 = *(const float4*)&Yo[mm * 34 + ky0 + 2];
        float yer[4] = {e01.x, e01.z, e23.x, e23.z};
        float yei[4] = {e01.y, e01.w, e23.y, e23.w};
        float yor[4] = {o01.x, o01.z, o23.x, o23.z};
        float yoi[4] = {o01.y, o01.w, o23.y, o23.w};
#pragma unroll
        for (int j = 0; j < 2; j++) {
            float2 e = Eh[(hl + j) * 34 + mm];
#pragma unroll
            for (int q = 0; q < 4; q++) {
                aer[j][q] += e.x * yer[q] - e.y * yei[q];
                aei[j][q] += e.x * yei[q] + e.y * yer[q];
                aor[j][q] += e.x * yor[q] - e.y * yoi[q];
                aoi[j][q] += e.x * yoi[q] + e.y * yor[q];
            }
        }
    }
#pragma unroll
    for (int j = 0; j < 2; j++) {
        int hp = h0 + hl + j;
        float2 w = g_w256[hp];
        float pr[4], pi[4], mr[4], mi[4];
#pragma unroll
        for (int q = 0; q < 4; q++) {
            float sr = aor[j][q] * w.x - aoi[j][q] * w.y;
            float si = aoi[j][q] * w.x + aor[j][q] * w.y;
            pr[q] = aer[j][q] + sr; pi[q] = aei[j][q] + si;
            mr[q] = aer[j][q] - sr; mi[q] = aei[j][q] - si;
        }
        size_t b1 = ((size_t)img * Hc + hp) * KY + ky0;
        size_t b2 = ((size_t)img * Hc + hp + 128) * KY + ky0;
        *(float4*)&g_T2[b1]     = make_float4(pr[0], pi[0], pr[1], pi[1]);
        *(float4*)&g_T2[b1 + 2] = make_float4(pr[2], pi[2], pr[3], pi[3]);
        *(float4*)&g_T2[b2]     = make_float4(mr[0], mi[0], mr[1], mi[1]);
        *(float4*)&g_T2[b2 + 2] = make_float4(mr[2], mi[2], mr[3], mi[3]);
    }
}

// ------- stage E: ky-parity-folded inverse W-DFT + w0/w128 columns ---------
__global__ void __launch_bounds__(256) kE(const float* __restrict__ bias,
                                          float* __restrict__ out) {
    __shared__ __align__(16) float2 T2s[32 * 66];   // [ky][h]
    __shared__ __align__(16) float2 csE[32 * 34];   // [ky][s_local]
    int img = blockIdx.z;
    int hb  = blockIdx.y;            // 0..3 (64 h)
    int wb  = blockIdx.x;            // 0..1 (32 s)
    int t = threadIdx.x;
    int sl = t & 15;                 // s = sl and sl+16
    int hq = (t >> 4) * 4;           // 4 h per thread

#pragma unroll
    for (int r = 0; r < 8; r++) {
        int e = t + r * 256; int ky = e & 31, h = e >> 5;
        T2s[ky * 66 + h] = g_T2[((size_t)img * Hc + hb * 64 + h) * KY + ky];
    }
#pragma unroll
    for (int r = 0; r < 4; r++) {
        int e = t + r * 256; int ky = e >> 5, s = e & 31;
        csE[ky * 34 + s] = g_cs2E[ky * 64 + wb * 32 + s];
    }
    __syncthreads();

    float Pe[4][2], Po[4][2], Qe[4][2], Qo[4][2];
#pragma unroll
    for (int j = 0; j < 4; j++)
#pragma unroll
        for (int q = 0; q < 2; q++) { Pe[j][q]=0.f; Po[j][q]=0.f; Qe[j][q]=0.f; Qo[j][q]=0.f; }

#pragma unroll
    for (int ky = 0; ky < 32; ky++) {
        float4 t01 = *(const float4*)&T2s[ky * 66 + hq];
        float4 t23 = *(const float4*)&T2s[ky * 66 + hq + 2];
        float trv[4] = {t01.x, t01.z, t23.x, t23.z};
        float tiv[4] = {t01.y, t01.w, t23.y, t23.w};
        float2 ca = csE[ky * 34 + sl];
        float2 cb = csE[ky * 34 + sl + 16];
        float cc[2] = {ca.x, cb.x};
        float ss[2] = {ca.y, cb.y};
        if ((ky & 1) == 0) {
#pragma unroll
            for (int j = 0; j < 4; j++)
#pragma unroll
                for (int q = 0; q < 2; q++) {
                    Pe[j][q] += cc[q] * trv[j];
                    Qe[j][q] += ss[q] * tiv[j];
                }
        } else {
#pragma unroll
            for (int j = 0; j < 4; j++)
#pragma unroll
                for (int q = 0; q < 2; q++) {
                    Po[j][q] += cc[q] * trv[j];
                    Qo[j][q] += ss[q] * tiv[j];
                }
        }
    }

    float bv = bias[img & 31];
#pragma unroll
    for (int j = 0; j < 4; j++) {
        size_t row = ((size_t)img * Hc + hb * 64 + hq + j) * Wc;
#pragma unroll
        for (int q = 0; q < 2; q++) {
            int tw = wb * 32 + sl + 16 * q + 1;    // half-warp writes 16 consecutive w
            float Pp = Pe[j][q] + Po[j][q], Pm = Pe[j][q] - Po[j][q];
            float Qp = Qe[j][q] + Qo[j][q], Qm = Qe[j][q] - Qo[j][q];
            out[row + tw]        = Pp - Qp + bv;
            out[row + 256 - tw]  = Pp + Qp + bv;
            out[row + 128 - tw]  = Pm + Qm + bv;
            out[row + 128 + tw]  = Pm - Qm + bv;
        }
    }

    // merged former kE0: w = 0 and w = 128 columns (lanes sl<2 of wb==0)
    if (wb == 0 && sl < 2) {
        float acc[4] = {0.f, 0.f, 0.f, 0.f};
#pragma unroll 8
        for (int ky = 0; ky < 32; ky++) {
            float coef = ((ky == 0) ? 1.f : 2.f) * (1.f / 65536.f);
            float f = (sl == 1 && (ky & 1)) ? -coef : coef;
#pragma unroll
            for (int j = 0; j < 4; j++)
                acc[j] += f * T2s[ky * 66 + hq + j].x;
        }
        int wcol = (sl == 0) ? 0 : 128;
#pragma unroll
        for (int j = 0; j < 4; j++) {
            size_t row = ((size_t)img * Hc + hb * 64 + hq + j) * Wc;
            out[row + wcol] = acc[j] + bv;
        }
    }
}

// ---------------- launch ----------------
extern "C" void kernel_launch(void* const* d_in, const int* in_sizes, int n_in,
                              void* d_out, int out_size) {
    const float* x    = (const float*)d_in[0];
    const float* w1r  = (const float*)d_in[1];
    const float* w1i  = (const float*)d_in[2];
    const float* w2r  = (const float*)d_in[3];
    const float* w2i  = (const float*)d_in[4];
    const float* bias = (const float*)d_in[5];
    float* out = (float*)d_out;

    k_tables<<<48, 256>>>();
    k_wtrans<<<dim3(32, 32, 2), dim3(32, 8)>>>(w1r, w1i, w2r, w2i);
    kA<<<dim3(4, 256), 128>>>(x);
    kB<<<dim3(4, 256), 128>>>();
    kC<<<512, 256>>>();
    kD<<<dim3(4, 256), 128>>>();
    kE<<<dim3(2, 4, 256), 256>>>(bias, out);
}